// round 11
// baseline (speedup 1.0000x reference)
#include <cuda_runtime.h>
#include <cstdint>

// TaylorExp: out row (273) = [1, x*0.5 (16), outer(sx,sx) (256)]
// sx = x * sqrt(1/(sqrt(2)*sqrt(16)))
//
// Round-11: R9 champion (2-chunk double-buffered TMA pipeline, evict_first
// stores) + streaming input loads (__ldcs): input is read exactly once, so
// keep it from displacing the output write stream in L2.

#define QUAD_SQRT_SCALE 0.42044820762685725f
#define T1_SCALE        0.5f
#define ROWS_PER_CHUNK  4
#define CHUNKS_PER_CTA  2
#define THREADS         128
#define ROW_LEN         273
#define CHUNK_FLOATS    (ROWS_PER_CHUNK * ROW_LEN)   // 1092
#define CHUNK_BYTES     (CHUNK_FLOATS * 4)           // 4368 = 273*16

__device__ __forceinline__ void compute_chunk(
    const float* __restrict__ x, float* __restrict__ sbuf,
    int chunk, int rows, int warp, int lane)
{
    const int row = chunk * ROWS_PER_CHUNK + warp;
    if (row >= rows) return;

    float* __restrict__ srow = sbuf + warp * ROW_LEN;
    float xv = (lane < 16) ? __ldcs(x + (size_t)row * 16 + lane) : 0.0f;

    if (lane < 16)  srow[1 + lane] = xv * T1_SCALE;
    if (lane == 16) srow[0] = 1.0f;

    float sx = xv * QUAD_SQRT_SCALE;
    #pragma unroll
    for (int k = 0; k < 8; k++) {
        int q = lane + 32 * k;                       // 0..255
        float vr = __shfl_sync(0xffffffffu, sx, q >> 4);
        float vc = __shfl_sync(0xffffffffu, sx, q & 15);
        srow[17 + q] = vr * vc;
    }
}

__device__ __forceinline__ void issue_store(
    float* __restrict__ out, const float* __restrict__ sbuf, int chunk)
{
    uint32_t saddr = (uint32_t)__cvta_generic_to_shared(sbuf);
    float* gdst = out + (size_t)chunk * CHUNK_FLOATS;
    asm volatile("fence.proxy.async.shared::cta;" ::: "memory");
    asm volatile(
        "{\n\t"
        ".reg .b64 pol;\n\t"
        "createpolicy.fractional.L2::evict_first.b64 pol, 1.0;\n\t"
        "cp.async.bulk.global.shared::cta.bulk_group.L2::cache_hint"
        " [%0], [%1], %2, pol;\n\t"
        "}"
        :: "l"(gdst), "r"(saddr), "r"((uint32_t)CHUNK_BYTES)
        : "memory");
    asm volatile("cp.async.bulk.commit_group;" ::: "memory");
}

__global__ void __launch_bounds__(THREADS) taylor_exp_kernel(
    const float* __restrict__ x,
    float* __restrict__ out,
    int rows)
{
    __shared__ __align__(16) float s[CHUNKS_PER_CTA][CHUNK_FLOATS];

    const int warp = threadIdx.x >> 5;
    const int lane = threadIdx.x & 31;
    const int chunk0 = blockIdx.x * CHUNKS_PER_CTA;

    // ---- chunk 0: compute -> issue store (no wait) ----
    compute_chunk(x, s[0], chunk0, rows, warp, lane);
    __syncthreads();

    const int valid0 = min(ROWS_PER_CHUNK, rows - chunk0 * ROWS_PER_CHUNK);
    bool issued = false;
    if (valid0 == ROWS_PER_CHUNK) {
        if (threadIdx.x == 0) issue_store(out, s[0], chunk0);
        issued = true;
    } else if (valid0 > 0) {
        const size_t base = (size_t)chunk0 * CHUNK_FLOATS;
        const int nfloats = valid0 * ROW_LEN;
        for (int i = threadIdx.x; i < nfloats; i += THREADS)
            out[base + i] = s[0][i];
    }

    // ---- chunk 1: compute (overlaps chunk-0 drain) -> issue store ----
    const int chunk1 = chunk0 + 1;
    const int valid1 = min(ROWS_PER_CHUNK, rows - chunk1 * ROWS_PER_CHUNK);
    if (valid1 > 0) {
        compute_chunk(x, s[1], chunk1, rows, warp, lane);
        __syncthreads();

        if (valid1 == ROWS_PER_CHUNK) {
            if (threadIdx.x == 0) issue_store(out, s[1], chunk1);
            issued = true;
        } else {
            const size_t base = (size_t)chunk1 * CHUNK_FLOATS;
            const int nfloats = valid1 * ROW_LEN;
            for (int i = threadIdx.x; i < nfloats; i += THREADS)
                out[base + i] = s[1][i];
        }
    }

    // single drain-wait for both bulk stores (smem reuse safety before exit)
    if (issued && threadIdx.x == 0)
        asm volatile("cp.async.bulk.wait_group 0;" ::: "memory");
}

extern "C" void kernel_launch(void* const* d_in, const int* in_sizes, int n_in,
                              void* d_out, int out_size)
{
    const float* x = (const float*)d_in[0];
    float* out = (float*)d_out;

    int rows = in_sizes[0] / 16;
    int rows_per_cta = ROWS_PER_CHUNK * CHUNKS_PER_CTA;       // 8
    int blocks = (rows + rows_per_cta - 1) / rows_per_cta;

    taylor_exp_kernel<<<blocks, THREADS>>>(x, out, rows);
}

// round 12
// speedup vs baseline: 1.1896x; 1.1896x over previous
#include <cuda_runtime.h>
#include <cstdint>

// TaylorExp: out row (273) = [1, x*0.5 (16), outer(sx,sx) (256)]
// sx = x * sqrt(1/(sqrt(2)*sqrt(16)))
//
// Round-12: R9 champion (2-chunk double-buffered TMA pipeline, evict_first
// bulk stores, 128-thread CTAs) + upfront prefetch of BOTH chunks' inputs so
// chunk 1's global-load latency is hidden under chunk 0's compute/store.

#define QUAD_SQRT_SCALE 0.42044820762685725f
#define T1_SCALE        0.5f
#define ROWS_PER_CHUNK  4
#define CHUNKS_PER_CTA  2
#define THREADS         128
#define ROW_LEN         273
#define CHUNK_FLOATS    (ROWS_PER_CHUNK * ROW_LEN)   // 1092
#define CHUNK_BYTES     (CHUNK_FLOATS * 4)           // 4368 = 273*16

__device__ __forceinline__ void compute_chunk_from_val(
    float xv, float* __restrict__ sbuf, int warp, int lane)
{
    float* __restrict__ srow = sbuf + warp * ROW_LEN;

    if (lane < 16)  srow[1 + lane] = xv * T1_SCALE;
    if (lane == 16) srow[0] = 1.0f;

    float sx = xv * QUAD_SQRT_SCALE;
    #pragma unroll
    for (int k = 0; k < 8; k++) {
        int q = lane + 32 * k;                       // 0..255
        float vr = __shfl_sync(0xffffffffu, sx, q >> 4);
        float vc = __shfl_sync(0xffffffffu, sx, q & 15);
        srow[17 + q] = vr * vc;
    }
}

__device__ __forceinline__ void issue_store(
    float* __restrict__ out, const float* __restrict__ sbuf, int chunk)
{
    uint32_t saddr = (uint32_t)__cvta_generic_to_shared(sbuf);
    float* gdst = out + (size_t)chunk * CHUNK_FLOATS;
    asm volatile("fence.proxy.async.shared::cta;" ::: "memory");
    asm volatile(
        "{\n\t"
        ".reg .b64 pol;\n\t"
        "createpolicy.fractional.L2::evict_first.b64 pol, 1.0;\n\t"
        "cp.async.bulk.global.shared::cta.bulk_group.L2::cache_hint"
        " [%0], [%1], %2, pol;\n\t"
        "}"
        :: "l"(gdst), "r"(saddr), "r"((uint32_t)CHUNK_BYTES)
        : "memory");
    asm volatile("cp.async.bulk.commit_group;" ::: "memory");
}

__global__ void __launch_bounds__(THREADS) taylor_exp_kernel(
    const float* __restrict__ x,
    float* __restrict__ out,
    int rows)
{
    __shared__ __align__(16) float s[CHUNKS_PER_CTA][CHUNK_FLOATS];

    const int warp = threadIdx.x >> 5;
    const int lane = threadIdx.x & 31;
    const int chunk0 = blockIdx.x * CHUNKS_PER_CTA;
    const int chunk1 = chunk0 + 1;

    const int row0 = chunk0 * ROWS_PER_CHUNK + warp;
    const int row1 = chunk1 * ROWS_PER_CHUNK + warp;

    // prefetch BOTH chunks' inputs (independent loads, MLP=2) so chunk 1's
    // load latency is hidden under chunk 0's compute + store issue.
    float xv0 = (lane < 16 && row0 < rows) ? x[(size_t)row0 * 16 + lane] : 0.0f;
    float xv1 = (lane < 16 && row1 < rows) ? x[(size_t)row1 * 16 + lane] : 0.0f;

    // ---- chunk 0: compute -> issue store (no wait) ----
    if (row0 < rows) compute_chunk_from_val(xv0, s[0], warp, lane);
    __syncthreads();

    const int valid0 = min(ROWS_PER_CHUNK, rows - chunk0 * ROWS_PER_CHUNK);
    bool issued = false;
    if (valid0 == ROWS_PER_CHUNK) {
        if (threadIdx.x == 0) issue_store(out, s[0], chunk0);
        issued = true;
    } else if (valid0 > 0) {
        const size_t base = (size_t)chunk0 * CHUNK_FLOATS;
        const int nfloats = valid0 * ROW_LEN;
        for (int i = threadIdx.x; i < nfloats; i += THREADS)
            out[base + i] = s[0][i];
    }

    // ---- chunk 1: compute (overlaps chunk-0 drain) -> issue store ----
    const int valid1 = min(ROWS_PER_CHUNK, rows - chunk1 * ROWS_PER_CHUNK);
    if (valid1 > 0) {
        if (row1 < rows) compute_chunk_from_val(xv1, s[1], warp, lane);
        __syncthreads();

        if (valid1 == ROWS_PER_CHUNK) {
            if (threadIdx.x == 0) issue_store(out, s[1], chunk1);
            issued = true;
        } else {
            const size_t base = (size_t)chunk1 * CHUNK_FLOATS;
            const int nfloats = valid1 * ROW_LEN;
            for (int i = threadIdx.x; i < nfloats; i += THREADS)
                out[base + i] = s[1][i];
        }
    }

    // single drain-wait for both bulk stores (smem reuse safety before exit)
    if (issued && threadIdx.x == 0)
        asm volatile("cp.async.bulk.wait_group 0;" ::: "memory");
}

extern "C" void kernel_launch(void* const* d_in, const int* in_sizes, int n_in,
                              void* d_out, int out_size)
{
    const float* x = (const float*)d_in[0];
    float* out = (float*)d_out;

    int rows = in_sizes[0] / 16;
    int rows_per_cta = ROWS_PER_CHUNK * CHUNKS_PER_CTA;       // 8
    int blocks = (rows + rows_per_cta - 1) / rows_per_cta;

    taylor_exp_kernel<<<blocks, THREADS>>>(x, out, rows);
}